// round 16
// baseline (speedup 1.0000x reference)
#include <cuda_runtime.h>
#include <cuda_fp16.h>
#include <cstdint>

// Problem constants
#define BB 4
#define SS 8192
#define DD 512
#define HH 8
#define HDIM 64
#define RR 64
#define BSROWS (BB * SS)      // 32768
#define BH (BB * HH)          // 32
#define NCHUNK 16

// -------- scratch (static device globals; no allocation) --------
__device__ __half g_xhi[BSROWS * DD];
__device__ __half g_xlo[BSROWS * DD];
__device__ __half g_vh[BSROWS * DD];
__device__ __half g_ahi[BSROWS * DD];
__device__ __half g_wth[4 * DD * DD];     // fp16 transposed weights
__device__ float g_biasqkv[3 * DD];
__device__ __half g_gint_hi[2][128 * 64];
__device__ __half g_gint_lo[2][128 * 64];
__device__ __half g_pqh[BH * SS * RR];    // phiq [bh][s][r], fp16 hi only
__device__ __half g_pkth[BH * RR * SS];   // phikT [bh][r][s], fp16 hi only
__device__ float g_kvtp[BH * NCHUNK * HDIM * RR];
__device__ float g_ksp[BH * NCHUNK * RR];
__device__ __half g_kvth[BH * HDIM * RR];
__device__ float g_ks[BH * RR];

// ============================================================
// helpers
// ============================================================
__device__ __forceinline__ uint32_t smem_to_u32(const void* p) {
    uint32_t a;
    asm("{ .reg .u64 t; cvta.to.shared.u64 t, %1; cvt.u32.u64 %0, t; }"
        : "=r"(a) : "l"(p));
    return a;
}
__device__ __forceinline__ void ldsm4(uint32_t& r0, uint32_t& r1,
                                      uint32_t& r2, uint32_t& r3,
                                      uint32_t addr) {
    asm volatile("ldmatrix.sync.aligned.m8n8.x4.shared.b16 {%0,%1,%2,%3}, [%4];"
                 : "=r"(r0), "=r"(r1), "=r"(r2), "=r"(r3) : "r"(addr));
}
__device__ __forceinline__ void ldsm4t(uint32_t& r0, uint32_t& r1,
                                       uint32_t& r2, uint32_t& r3,
                                       uint32_t addr) {
    asm volatile("ldmatrix.sync.aligned.m8n8.x4.trans.shared.b16 {%0,%1,%2,%3}, [%4];"
                 : "=r"(r0), "=r"(r1), "=r"(r2), "=r"(r3) : "r"(addr));
}
__device__ __forceinline__ void mma16816(float* d, const uint32_t* a,
                                         const uint32_t* b) {
    asm volatile(
        "mma.sync.aligned.m16n8k16.row.col.f32.f16.f16.f32 "
        "{%0,%1,%2,%3}, {%4,%5,%6,%7}, {%8,%9}, {%0,%1,%2,%3};"
        : "+f"(d[0]), "+f"(d[1]), "+f"(d[2]), "+f"(d[3])
        : "r"(a[0]), "r"(a[1]), "r"(a[2]), "r"(a[3]), "r"(b[0]), "r"(b[1]));
}
#define CP_ASYNC16(dst, src) \
    asm volatile("cp.async.cg.shared.global [%0], [%1], 16;" :: "r"(dst), "l"(src))
#define CP_COMMIT() asm volatile("cp.async.commit_group;" ::: "memory")
#define CP_WAIT(n)  asm volatile("cp.async.wait_group %0;" :: "n"(n) : "memory")

__device__ __forceinline__ void split4h(float4 v, uint2& hi, uint2& lo) {
    __half h0 = __float2half_rn(v.x), h1 = __float2half_rn(v.y);
    __half h2 = __float2half_rn(v.z), h3 = __float2half_rn(v.w);
    float r0 = v.x - __half2float(h0), r1 = v.y - __half2float(h1);
    float r2 = v.z - __half2float(h2), r3 = v.w - __half2float(h3);
    __half l0 = __float2half_rn(r0), l1 = __float2half_rn(r1);
    __half l2 = __float2half_rn(r2), l3 = __float2half_rn(r3);
    hi.x = ((uint32_t)__half_as_ushort(h1) << 16) | __half_as_ushort(h0);
    hi.y = ((uint32_t)__half_as_ushort(h3) << 16) | __half_as_ushort(h2);
    lo.x = ((uint32_t)__half_as_ushort(l1) << 16) | __half_as_ushort(l0);
    lo.y = ((uint32_t)__half_as_ushort(l3) << 16) | __half_as_ushort(l2);
}
__device__ __forceinline__ void split2h(float a, float b, uint32_t& hp, uint32_t& lp) {
    __half h0 = __float2half_rn(a), h1 = __float2half_rn(b);
    float l0 = a - __half2float(h0), l1 = b - __half2float(h1);
    __half e0 = __float2half_rn(l0), e1 = __float2half_rn(l1);
    hp = ((uint32_t)__half_as_ushort(h1) << 16) | __half_as_ushort(h0);
    lp = ((uint32_t)__half_as_ushort(e1) << 16) | __half_as_ushort(e0);
}
__device__ __forceinline__ uint32_t pack2h(float a, float b) {
    __half h0 = __float2half_rn(a), h1 = __float2half_rn(b);
    return ((uint32_t)__half_as_ushort(h1) << 16) | __half_as_ushort(h0);
}

// ============================================================
// prep kernels
// ============================================================
__global__ __launch_bounds__(256) void split_fp32(
    const float* __restrict__ X, __half* __restrict__ Xh,
    __half* __restrict__ Xl)
{
    int i = blockIdx.x * 256 + threadIdx.x;
    float4 v = ((const float4*)X)[i];
    uint2 hi, lo;
    split4h(v, hi, lo);
    ((uint2*)Xh)[i] = hi;
    ((uint2*)Xl)[i] = lo;
}

__global__ __launch_bounds__(256) void transpose_h4(
    const float* __restrict__ Wq, const float* __restrict__ Wk,
    const float* __restrict__ Wv, const float* __restrict__ Wp,
    const float* __restrict__ gq, const float* __restrict__ gk,
    __half* __restrict__ Th)
{
    __shared__ float t[32][33];
    const int z = blockIdx.z;
    const float* W = z == 0 ? Wq : (z == 1 ? Wk : (z == 2 ? Wv : Wp));
    const float scale = z == 0 ? gq[0] : (z == 1 ? gk[0] : 1.0f);
    const int rowoff = z * DD;
    int bx = blockIdx.x * 32, by = blockIdx.y * 32;
    int x = threadIdx.x & 31, y = threadIdx.x >> 5;
    for (int i = y; i < 32; i += 8) t[i][x] = W[(size_t)(by + i) * DD + bx + x];
    __syncthreads();
    for (int i = y; i < 32; i += 8)
        Th[(size_t)(rowoff + bx + i) * DD + by + x] = __float2half_rn(t[x][i] * scale);
}

__global__ __launch_bounds__(256) void misc_prep(
    const float* __restrict__ qG1, const float* __restrict__ qG2,
    const float* __restrict__ kG1, const float* __restrict__ kG2,
    const float* bq, const float* bk, const float* bv,
    const float* gq, const float* betq,
    const float* gk, const float* betk,
    float* bout)
{
    const int blk = blockIdx.x;
    if (blk < 2) {
        const int set = blk;
        const float* G1 = set ? kG1 : qG1;
        const float* G2 = set ? kG2 : qG2;
        __half* Oh = g_gint_hi[set];
        __half* Ol = g_gint_lo[set];
        for (int it = 0; it < 32; it++) {
            int idx = it * 256 + threadIdx.x;
            int n = idx >> 6, k = idx & 63;
            float v = ((n & 1) ? G2 : G1)[k * 64 + (n >> 1)];
            __half h = __float2half_rn(v);
            Oh[idx] = h;
            Ol[idx] = __float2half_rn(v - __half2float(h));
        }
    } else {
        int i = (blk - 2) * 256 + threadIdx.x;
        if (i < DD) bout[i] = gq[0] * bq[i] + betq[0];
        else if (i < 2 * DD) bout[i] = gk[0] * bk[i - DD] + betk[0];
        else if (i < 3 * DD) bout[i] = bv[i - 2 * DD];
    }
}

// ============================================================
// fp16 split GEMM + fused sketch epilogue.
// 256 threads, 8 warps (2m x 4n), warp tile 64x32, CTA 128x128.
// 2 CTAs per SM (launch_bounds(256,2)) for barrier-decoupled overlap.
// QKV grid (12, 256): sel = bn>>2 (0=q,1=k,2=v); q/k tile = 2 heads.
// ============================================================
#define BKC 32
#define NKCH (DD / BKC)          // 16
#define ROWB 80
#define TILE_A (128 * ROWB)      // 10240
#define ST_AHI 0
#define ST_ALO TILE_A
#define ST_BH (2 * TILE_A)
#define STAGEB (3 * TILE_A)      // 30720
#define PIPE 3
#define OFF80(row, ch) ((uint32_t)((row) * ROWB + ((ch) << 4)))
// fused sketch regions (reuse smem after mainloop): 2 heads per CTA
#define FZ_HEAD 36864            // per-head z region: hi 18432 + lo 18432
#define FZ_LO 18432
#define FG_OFF (2 * FZ_HEAD)     // 73728
#define FG_LO 18432
#define GEMM_SMEM (FG_OFF + 2 * FG_LO)   // 110592 (> PIPE*STAGEB = 92160)
#define SOFF144(row, ch) ((uint32_t)((row) * 144 + ((ch) << 4)))

__global__ __launch_bounds__(256, 2) void mma_gemm(
    const __half* __restrict__ Ahi, const __half* __restrict__ Alo,
    const __half* __restrict__ Bh, const float* __restrict__ bias,
    __half* __restrict__ pqh, __half* __restrict__ pkth,
    __half* __restrict__ vh, float* __restrict__ ofp32)
{
    extern __shared__ char smem[];
    const uint32_t sb = smem_to_u32(smem);

    const int tid = threadIdx.x;
    const int wid = tid >> 5, lane = tid & 31;
    const int bn = blockIdx.x, bm = blockIdx.y;
    const int warp_m = wid & 1, warp_n = wid >> 1;
    const bool useAlo = (Alo != nullptr) && (bn < 8);

    const __half* Ahi_b = Ahi + (size_t)bm * 128 * DD;
    const __half* Alo_b = useAlo ? Alo + (size_t)bm * 128 * DD : Ahi_b;
    const __half* Bh_b = Bh + (size_t)bn * 128 * DD;

    const int lrow = tid >> 2;    // 0..63
    const int lch = tid & 3;

    auto load_chunk = [&](int c, int s) {
        const uint32_t stg = sb + s * STAGEB;
        const int k0 = c * BKC;
#pragma unroll
        for (int sw = 0; sw < 2; sw++) {
            const int row = sw * 64 + lrow;
            const size_t go = (size_t)row * DD + k0 + lch * 8;
            const uint32_t so = OFF80(row, lch);
            CP_ASYNC16(stg + ST_AHI + so, Ahi_b + go);
            if (useAlo) CP_ASYNC16(stg + ST_ALO + so, Alo_b + go);
            CP_ASYNC16(stg + ST_BH + so, Bh_b + go);
        }
    };

    float acc[4][4][4];
#pragma unroll
    for (int i = 0; i < 4; i++)
#pragma unroll
        for (int j = 0; j < 4; j++)
#pragma unroll
            for (int e = 0; e < 4; e++) acc[i][j][e] = 0.f;

    const int mat = lane >> 3, mr = lane & 7;
    const int a_row_b = warp_m * 64 + (mat & 1) * 8 + mr;
    const int b_row_b = warp_n * 32 + (mat & 1) * 8 + mr;
    const int mchunk = mat >> 1;

    load_chunk(0, 0); CP_COMMIT();
    load_chunk(1, 1); CP_COMMIT();

    for (int c = 0; c < NKCH; c++) {
        CP_WAIT(1);
        __syncthreads();
        if (c + 2 < NKCH) load_chunk(c + 2, (c + 2) % PIPE);
        CP_COMMIT();

        const uint32_t stg = sb + (c % PIPE) * STAGEB;
#pragma unroll
        for (int kk = 0; kk < 2; kk++) {
            const int ch = kk * 2 + mchunk;
            uint32_t ahi[4][4], alo[4][4];
#pragma unroll
            for (int im = 0; im < 4; im++) {
                const int row = a_row_b + im * 16;
                ldsm4(ahi[im][0], ahi[im][1], ahi[im][2], ahi[im][3],
                      stg + ST_AHI + OFF80(row, ch));
                if (useAlo)
                    ldsm4(alo[im][0], alo[im][1], alo[im][2], alo[im][3],
                          stg + ST_ALO + OFF80(row, ch));
            }
#pragma unroll
            for (int j16 = 0; j16 < 2; j16++) {
                const int row = b_row_b + j16 * 16;
                uint32_t h0, h1, h2, h3;
                ldsm4(h0, h1, h2, h3, stg + ST_BH + OFF80(row, ch));
                uint32_t bh0[2] = {h0, h2}, bh1[2] = {h1, h3};
#pragma unroll
                for (int im = 0; im < 4; im++) {
                    mma16816(acc[im][j16 * 2], ahi[im], bh0);
                    mma16816(acc[im][j16 * 2 + 1], ahi[im], bh1);
                    if (useAlo) {
                        mma16816(acc[im][j16 * 2], alo[im], bh0);
                        mma16816(acc[im][j16 * 2 + 1], alo[im], bh1);
                    }
                }
            }
        }
    }

    const int erow = lane >> 2, ecol = (lane & 3) * 2;

    if (ofp32) {
        // ---- projection epilogue: fp32 out ----
        const int colbase = bn * 128;
#pragma unroll
        for (int im = 0; im < 4; im++) {
            const size_t row0 = (size_t)bm * 128 + warp_m * 64 + im * 16 + erow;
#pragma unroll
            for (int j = 0; j < 4; j++) {
                const int cofs = warp_n * 32 + j * 8 + ecol;
                float2 b2 = *(const float2*)&bias[colbase + cofs];
                float2 q0 = make_float2(acc[im][j][0] + b2.x, acc[im][j][1] + b2.y);
                float2 q1 = make_float2(acc[im][j][2] + b2.x, acc[im][j][3] + b2.y);
                *(float2*)&ofp32[row0 * DD + colbase + cofs] = q0;
                *(float2*)&ofp32[(row0 + 8) * DD + colbase + cofs] = q1;
            }
        }
        return;
    }

    const int sel = bn >> 2;
    if (sel == 2) {
        // ---- v epilogue: fp16 hi only ----
        const int colbase = (bn & 3) * 128;
#pragma unroll
        for (int im = 0; im < 4; im++) {
            const size_t row0 = (size_t)bm * 128 + warp_m * 64 + im * 16 + erow;
#pragma unroll
            for (int j = 0; j < 4; j++) {
                const int cofs = warp_n * 32 + j * 8 + ecol;
                float2 b2 = *(const float2*)&bias[bn * 128 + cofs];
                *(uint32_t*)(vh + row0 * DD + colbase + cofs) =
                    pack2h(acc[im][j][0] + b2.x, acc[im][j][1] + b2.y);
                *(uint32_t*)(vh + (row0 + 8) * DD + colbase + cofs) =
                    pack2h(acc[im][j][2] + b2.x, acc[im][j][3] + b2.y);
            }
        }
        return;
    }

    // ---- fused sketch epilogue (sel 0 = q, 1 = k); tile = 2 heads ----
    CP_WAIT(0);
    __syncthreads();

    // stage z = acc + bias as fp16 hi/lo, per head (2 heads per CTA tile)
#pragma unroll
    for (int im = 0; im < 4; im++) {
        const int row = warp_m * 64 + im * 16 + erow;
#pragma unroll
        for (int j = 0; j < 4; j++) {
            const int cofs = warp_n * 32 + j * 8 + ecol;
            const int head = cofs >> 6, c = cofs & 63;
            float2 b2 = *(const float2*)&bias[bn * 128 + cofs];
            uint32_t hp, lp;
            split2h(acc[im][j][0] + b2.x, acc[im][j][1] + b2.y, hp, lp);
            *(uint32_t*)(smem + head * FZ_HEAD + row * 144 + c * 2) = hp;
            *(uint32_t*)(smem + head * FZ_HEAD + FZ_LO + row * 144 + c * 2) = lp;
            split2h(acc[im][j][2] + b2.x, acc[im][j][3] + b2.y, hp, lp);
            *(uint32_t*)(smem + head * FZ_HEAD + (row + 8) * 144 + c * 2) = hp;
            *(uint32_t*)(smem + head * FZ_HEAD + FZ_LO + (row + 8) * 144 + c * 2) = lp;
        }
    }
    // load G-int (hi/lo)
    {
        const __half* Gh = &g_gint_hi[sel][0];
        const __half* Gl = &g_gint_lo[sel][0];
#pragma unroll
        for (int it = 0; it < 4; it++) {
            const int cidx = it * 256 + tid;
            const int row = cidx >> 3, ch = cidx & 7;
            *(uint4*)(smem + FG_OFF + SOFF144(row, ch)) =
                *(const uint4*)((const char*)Gh + row * 128 + ch * 16);
            *(uint4*)(smem + FG_OFF + FG_LO + SOFF144(row, ch)) =
                *(const uint4*)((const char*)Gl + row * 128 + ch * 16);
        }
    }
    __syncthreads();

    // sketch warp mapping: 2m x 4n, warp tile 64x32 over [128 x 128]
    const int swm = wid & 1, swn = wid >> 1;
    const int a_row_s = swm * 64 + (mat & 1) * 8 + mr;
    const int b_row_s = swn * 32 + (mat & 1) * 8 + mr;
    const int b = bm >> 6;
    const int sbase = (bm & 63) * 128;
    const int g = lane >> 2, t4 = lane & 3;
    const float inv = 0.125f;

    for (int hd = 0; hd < 2; hd++) {
        const uint32_t zb = sb + hd * FZ_HEAD;

        float sk[4][4][4];
#pragma unroll
        for (int i = 0; i < 4; i++)
#pragma unroll
            for (int j = 0; j < 4; j++)
#pragma unroll
                for (int e = 0; e < 4; e++) sk[i][j][e] = 0.f;

#pragma unroll
        for (int kk = 0; kk < 4; kk++) {
            const int ch = kk * 2 + mchunk;
            uint32_t zhi[4][4], zlo[4][4];
#pragma unroll
            for (int im = 0; im < 4; im++) {
                const int row = a_row_s + im * 16;
                ldsm4(zhi[im][0], zhi[im][1], zhi[im][2], zhi[im][3],
                      zb + SOFF144(row, ch));
                ldsm4(zlo[im][0], zlo[im][1], zlo[im][2], zlo[im][3],
                      zb + FZ_LO + SOFF144(row, ch));
            }
#pragma unroll
            for (int j16 = 0; j16 < 2; j16++) {
                const int row = b_row_s + j16 * 16;
                uint32_t h0, h1, h2, h3, l0, l1, l2, l3;
                ldsm4(h0, h1, h2, h3, sb + FG_OFF + SOFF144(row, ch));
                ldsm4(l0, l1, l2, l3, sb + FG_OFF + FG_LO + SOFF144(row, ch));
                uint32_t gh0[2] = {h0, h2}, gh1[2] = {h1, h3};
                uint32_t gl0[2] = {l0, l2}, gl1[2] = {l1, l3};
#pragma unroll
                for (int im = 0; im < 4; im++) {
                    mma16816(sk[im][j16 * 2], zhi[im], gh0);
                    mma16816(sk[im][j16 * 2], zhi[im], gl0);
                    mma16816(sk[im][j16 * 2], zlo[im], gh0);
                    mma16816(sk[im][j16 * 2 + 1], zhi[im], gh1);
                    mma16816(sk[im][j16 * 2 + 1], zhi[im], gl1);
                    mma16816(sk[im][j16 * 2 + 1], zlo[im], gh1);
                }
            }
        }

        const int h = (bn & 3) * 2 + hd;
        const int bh2 = b * HH + h;
        __syncthreads();   // all warps done reading z[hd]; reuse for staging

        __half* SH = (__half*)(smem + hd * FZ_HEAD);
        if (sel == 0) {
            // stage phiq hi [128][72]
#pragma unroll
            for (int im = 0; im < 4; im++) {
                const int s0 = swm * 64 + im * 16 + g;
#pragma unroll
                for (int jn = 0; jn < 4; jn++) {
                    const int r = swn * 16 + jn * 4 + t4;
                    float h0 = inv * sk[im][jn][0] * sk[im][jn][1];
                    float h1 = inv * sk[im][jn][2] * sk[im][jn][3];
                    SH[s0 * 72 + r] = __float2half_rn(h0 * h0);
                    SH[(s0 + 8) * 72 + r] = __float2half_rn(h1 * h1);
                }
            }
            __syncthreads();
            const int row = tid >> 1, hf = tid & 1;
            size_t gbase = ((size_t)bh2 * SS + sbase + row) * RR + hf * 32;
            const uint4* srcH = (const uint4*)(smem + hd * FZ_HEAD + row * 144 + hf * 64);
#pragma unroll
            for (int i = 0; i < 4; i++) ((uint4*)(pqh + gbase))[i] = srcH[i];
        } else {
            // stage phikT hi [64 r][136 s]
#pragma unroll
            for (int im = 0; im < 4; im++) {
                const int s0 = swm * 64 + im * 16 + g;
#pragma unroll
                for (int jn = 0; jn < 4; jn++) {
                    const int r = swn * 16 + jn * 4 + t4;
                    float h0 = inv * sk[im][jn][0] * sk[im][jn][1];
                    float h1 = inv * sk[im][jn][2] * sk[im][jn][3];
                    SH[r * 136 + s0] = __float2half_rn(h0 * h0);
                    SH[r * 136 + s0 + 8] = __float2half_rn(h1 * h1);
                }
            }
            __syncthreads();
            const int r = tid >> 2, q4 = tid & 3;
            size_t gbase = ((size_t)bh2 * RR + r) * SS + sbase + q4 * 32;
            const uint4* srcH = (const uint4*)(smem + hd * FZ_HEAD + r * 272 + q4 * 64);
#pragma unroll
            for (int i = 0; i < 4; i++) ((uint4*)(pkth + gbase))[i] = srcH[i];
        }
    }
}

// ============================================================
// TC kvsum (1-pass, cp.async double-buffered steps)
// ============================================================
#define KV_STG 18432
#define KV_VHI 0
#define KV_PKH 9216

__global__ __launch_bounds__(256) void kvsum_tc(
    const __half* __restrict__ pkth, const __half* __restrict__ vh,
    float* __restrict__ kvtp, float* __restrict__ ksp)
{
    __shared__ __align__(16) char sm[2 * KV_STG];   // 36864
    const uint32_t sb = smem_to_u32(sm);

    const int tid = threadIdx.x;
    const int wid = tid >> 5, lane = tid & 31;
    const int chunk = blockIdx.x, bh = blockIdx.y;
    const int b = bh >> 3, h = bh & 7;
    const int warp_m = wid & 1, warp_n = wid >> 1;
    const int mat = lane >> 3, mr = lane & 7;
    const int g = lane >> 2, t = lane & 3;

    float acc[2][2][4];
#pragma unroll
    for (int i = 0; i < 2; i++)
#pragma unroll
        for (int j = 0; j < 2; j++)
#pragma unroll
            for (int e = 0; e < 4; e++) acc[i][j][e] = 0.f;
    float kacc = 0.f;

    const int lr = tid >> 2, lq = tid & 3;
    const int kr = tid & 63, kg = tid >> 6;

    auto load_step = [&](int step, int s) {
        const uint32_t stg = sb + s * KV_STG;
        const int s0 = chunk * 512 + step * 64;
        const size_t vo = (size_t)(b * SS + s0 + lr) * DD + h * HDIM + lq * 16;
        CP_ASYNC16(stg + KV_VHI + lr * 144 + lq * 32, vh + vo);
        CP_ASYNC16(stg + KV_VHI + lr * 144 + lq * 32 + 16, vh + vo + 8);
        const size_t po = ((size_t)bh * RR + lr) * SS + s0 + lq * 16;
        CP_ASYNC16(stg + KV_PKH + lr * 144 + lq * 32, pkth + po);
        CP_ASYNC16(stg + KV_PKH + lr * 144 + lq * 32 + 16, pkth + po + 8);
    };

    load_step(0, 0);
    CP_COMMIT();

    for (int step = 0; step < 8; step++) {
        if (step + 1 < 8) load_step(step + 1, (step + 1) & 1);
        CP_COMMIT();
        CP_WAIT(1);
        __syncthreads();

        const uint32_t stg = sb + (step & 1) * KV_STG;

#pragma unroll
        for (int c = 0; c < 16; c++) {
            int sc = kg * 16 + c;
            kacc += __half2float(*(__half*)((char*)sm + (step & 1) * KV_STG +
                                            KV_PKH + kr * 144 + sc * 2));
        }

#pragma unroll
        for (int kk = 0; kk < 4; kk++) {
            uint32_t ah[2][4];
#pragma unroll
            for (int im = 0; im < 2; im++) {
                const int d0 = warp_m * 32 + im * 16 + (mat & 1) * 8;
                const int srow = kk * 16 + ((mat >> 1) & 1) * 8 + mr;
                ldsm4t(ah[im][0], ah[im][1], ah[im][2], ah[im][3],
                       stg + KV_VHI + srow * 144 + d0 * 2);
            }
            const int rrow = warp_n * 16 + (mat & 1) * 8 + mr;
            const int chb = kk * 2 + (mat >> 1);
            uint32_t h0, h1, h2, h3;
            ldsm4(h0, h1, h2, h3, stg + KV_PKH + rrow * 144 + chb * 16);
            uint32_t bh0[2] = {h0, h2}, bh1[2] = {h1, h3};
#pragma unroll
            for (int im = 0; im < 2; im++) {
                mma16816(acc[im][0], ah[im], bh0);
                mma16816(acc[im][1], ah[im], bh1);
            }
        }
        __syncthreads();
    }

    float* outp = kvtp + ((size_t)bh * NCHUNK + chunk) * (HDIM * RR);
#pragma unroll
    for (int im = 0; im < 2; im++) {
        const int d = warp_m * 32 + im * 16 + g;
#pragma unroll
        for (int nb = 0; nb < 2; nb++) {
            const int r = warp_n * 16 + nb * 8 + t * 2;
            *(float2*)&outp[d * RR + r] =
                make_float2(acc[im][nb][0], acc[im][nb][1]);
            *(float2*)&outp[(d + 8) * RR + r] =
                make_float2(acc[im][nb][2], acc[im][nb][3]);
        }
    }
    __syncthreads();
    float* red = (float*)sm;
    red[kg * 64 + kr] = kacc;
    __syncthreads();
    if (tid < 64)
        ksp[((size_t)bh * NCHUNK + chunk) * RR + tid] =
            red[tid] + red[64 + tid] + red[128 + tid] + red[192 + tid];
}

__global__ void reduce2(const float* __restrict__ kvtp,
                        const float* __restrict__ ksp,
                        __half* __restrict__ kvth, float* __restrict__ ks)
{
    const int idx = blockIdx.x * 256 + threadIdx.x;
    const int total = BH * HDIM * RR;
    if (idx < total) {
        int bh = idx >> 12, e = idx & 4095;
        float s = 0.f;
#pragma unroll
        for (int c = 0; c < NCHUNK; c++)
            s += kvtp[((size_t)bh * NCHUNK + c) * 4096 + e];
        kvth[idx] = __float2half_rn(s);
    } else if (idx < total + BH * RR) {
        int j = idx - total;
        int bh = j >> 6, r = j & 63;
        float s = 0.f;
#pragma unroll
        for (int c = 0; c < NCHUNK; c++)
            s += ksp[((size_t)bh * NCHUNK + c) * RR + r];
        ks[j] = s;
    }
}

// ============================================================
// TC attn: 256 s-rows per CTA, one kv load, two MMA halves.
// ============================================================
#define AT_PQH 0
#define AT_KVH (256 * 144)                 // 36864
#define AT_KS  (AT_KVH + 64 * 144)         // + 9216
#define AT_DEN (AT_KS + 256)
#define AT_SMEM (AT_DEN + 1024)            // 47360

__global__ __launch_bounds__(256) void attn_tc(
    const __half* __restrict__ pqh, const __half* __restrict__ kvth,
    const float* __restrict__ ks,
    __half* __restrict__ ahi)
{
    __shared__ __align__(16) char sm[AT_SMEM];
    const uint32_t sb = smem_to_u32(sm);
    const int tid = threadIdx.x;
    const int wid = tid >> 5, lane = tid & 31;
    const int stile = blockIdx.x, bh = blockIdx.y;
    const int b = bh >> 3, h = bh & 7;
    const int sbase = stile * 256;
    const int warp_m = wid >> 1, warp_n = wid & 1;

    {
        const int row = tid;
        size_t gbase = ((size_t)bh * SS + sbase + row) * RR;
        uint4* dst = (uint4*)(sm + AT_PQH + row * 144);
#pragma unroll
        for (int i = 0; i < 8; i++) dst[i] = ((const uint4*)(pqh + gbase))[i];
    }
    {
        const int row = tid >> 2, q4 = tid & 3;
        size_t gbase = (size_t)bh * (HDIM * RR) + row * RR + q4 * 16;
        *(uint4*)(sm + AT_KVH + row * 144 + q4 * 32) = *(const uint4*)(kvth + gbase);
        *(uint4*)(sm + AT_KVH + row * 144 + q4 * 32 + 16) = *(const uint4*)(kvth + gbase + 8);
    }
    if (tid < 64) ((float*)(sm + AT_KS))[tid] = ks[bh * RR + tid];
    __syncthreads();

    {
        float d = 1e-6f;
        const float* kss = (const float*)(sm + AT_KS);
#pragma unroll 16
        for (int r = 0; r < 64; r++) {
            float p = __half2float(*(__half*)(sm + AT_PQH + tid * 144 + r * 2));
            d += p * kss[r];
        }
        ((float*)(sm + AT_DEN))[tid] = 1.0f / d;
    }
    __syncthreads();

    const int mat = lane >> 3, mr = lane & 7;
    const int b_row_b = warp_n * 32 + (mat & 1) * 8 + mr;
    const int mchunk = mat >> 1;
    const int g = lane >> 2, t = lane & 3;
    const float* rden = (const float*)(sm + AT_DEN);

#pragma unroll
    for (int half = 0; half < 2; half++) {
        const int hbase = half * 128;
        const int a_row_b = hbase + warp_m * 32 + (mat & 1) * 8 + mr;

        float acc[2][4][4];
#pragma unroll
        for (int i = 0; i < 2; i++)
#pragma unroll
            for (int j = 0; j < 4; j++)
#pragma unroll
                for (int e = 0; e < 4; e++) acc[i][j][e] = 0.f;

#pragma unroll
        for (int kk = 0; kk < 4; kk++) {
            const int ch = kk * 2 + mchunk;
            uint32_t ah[2][4];
#pragma unroll
            for (int im = 0; im < 2; im++) {
                const int row = a_row_b + im * 16;
                ldsm4(ah[im][0], ah[im][1], ah[im][2], ah[im][3],
                      sb + AT_PQH + row * 144 + ch * 16);
            }
#pragma unroll
            for (int nt = 0; nt < 2; nt++) {
                const int row = b_row_b + nt * 16;
                uint32_t h0, h1, h2, h3;
                ldsm4(h0, h1, h2, h3, sb + AT_KVH + row * 144 + ch * 16);
                uint32_t bh0[2] = {h0, h2}, bh1[2] = {h1, h3};
#pragma unroll
                for (int im = 0; im < 2; im++) {
                    mma16816(acc[im][nt * 2], ah[im], bh0);
                    mma16816(acc[im][nt * 2 + 1], ah[im], bh1);
                }
            }
        }

#pragma unroll
        for (int im = 0; im < 2; im++) {
            const int s0 = hbase + warp_m * 32 + im * 16 + g;
            const float rd0 = rden[s0], rd1 = rden[s0 + 8];
            const size_t row0 = ((size_t)b * SS + sbase + s0) * DD + h * HDIM;
            const size_t row1 = row0 + 8 * DD;
#pragma unroll
            for (int j8 = 0; j8 < 4; j8++) {
                const int d = warp_n * 32 + j8 * 8 + t * 2;
                *(uint32_t*)(ahi + row0 + d) =
                    pack2h(acc[im][j8][0] * rd0, acc[im][j8][1] * rd0);
                *(uint32_t*)(ahi + row1 + d) =
                    pack2h(acc[im][j8][2] * rd1, acc[im][j8][3] * rd1);
            }
        }
    }
}

// ============================================================
// launch
// ============================================================
extern "C" void kernel_launch(void* const* d_in, const int* in_sizes, int n_in,
                              void* d_out, int out_size)
{
    const float* x       = (const float*)d_in[0];
    const float* Wq      = (const float*)d_in[1];
    const float* bq      = (const float*)d_in[2];
    const float* Wk      = (const float*)d_in[3];
    const float* bk      = (const float*)d_in[4];
    const float* Wv      = (const float*)d_in[5];
    const float* bv      = (const float*)d_in[6];
    const float* Wp      = (const float*)d_in[7];
    const float* bp      = (const float*)d_in[8];
    const float* gamma_q = (const float*)d_in[9];
    const float* beta_q  = (const float*)d_in[10];
    const float* gamma_k = (const float*)d_in[11];
    const float* beta_k  = (const float*)d_in[12];
    const float* qG1     = (const float*)d_in[13];
    const float* qG2     = (const float*)d_in[14];
    const float* kG1     = (const float*)d_in[15];
    const float* kG2     = (const float*)d_in[16];
    float* out = (float*)d_out;

    float *p_bqkv, *p_kvtp, *p_ksp, *p_ks;
    __half *p_xhi, *p_xlo, *p_vh, *p_ahi, *p_wth;
    __half *p_pqh, *p_pkth, *p_kvth;
    cudaGetSymbolAddress((void**)&p_xhi, g_xhi);
    cudaGetSymbolAddress((void**)&p_xlo, g_xlo);
    cudaGetSymbolAddress((void**)&p_vh, g_vh);
    cudaGetSymbolAddress((void**)&p_ahi, g_ahi);
    cudaGetSymbolAddress((void**)&p_wth, g_wth);
    cudaGetSymbolAddress((void**)&p_bqkv, g_biasqkv);
    cudaGetSymbolAddress((void**)&p_pqh, g_pqh);
    cudaGetSymbolAddress((void**)&p_pkth, g_pkth);
    cudaGetSymbolAddress((void**)&p_kvtp, g_kvtp);
    cudaGetSymbolAddress((void**)&p_ksp, g_ksp);
    cudaGetSymbolAddress((void**)&p_kvth, g_kvth);
    cudaGetSymbolAddress((void**)&p_ks, g_ks);

    cudaFuncSetAttribute(mma_gemm, cudaFuncAttributeMaxDynamicSharedMemorySize,
                         GEMM_SMEM);

    // ---- prep (3 launches) ----
    split_fp32<<<BSROWS * DD / 4 / 256, 256>>>(x, p_xhi, p_xlo);               // 1
    misc_prep<<<8, 256>>>(qG1, qG2, kG1, kG2, bq, bk, bv,
                          gamma_q, beta_q, gamma_k, beta_k, p_bqkv);           // 2
    transpose_h4<<<dim3(16, 16, 4), 256>>>(Wq, Wk, Wv, Wp,
                                           gamma_q, gamma_k, p_wth);           // 3

    // ---- fused QKV GEMM + sketch (256 thr, 2 CTAs/SM) ----
    dim3 gq(12, BSROWS / 128);
    mma_gemm<<<gq, 256, GEMM_SMEM>>>(p_xhi, p_xlo, p_wth, p_bqkv,
                                     p_pqh, p_pkth, p_vh, nullptr);            // 4

    // ---- TC kvsum (pipelined) + reduce ----
    kvsum_tc<<<dim3(NCHUNK, BH), 256>>>(p_pkth, p_vh, p_kvtp, p_ksp);          // 5
    int red_total = BH * HDIM * RR + BH * RR;
    reduce2<<<(red_total + 255) / 256, 256>>>(p_kvtp, p_ksp, p_kvth, p_ks);

    // ---- TC attention output (256 rows/CTA, fp16 out) ----
    attn_tc<<<dim3(SS / 256, BH), 256>>>(p_pqh, p_kvth, p_ks, p_ahi);

    // ---- output projection (1-pass fp16, fp32 out) ----
    dim3 go(4, BSROWS / 128);
    mma_gemm<<<go, 256, GEMM_SMEM>>>(p_ahi, nullptr, p_wth + 1536 * DD, bp,
                                     nullptr, nullptr, nullptr, out);
}

// round 17
// speedup vs baseline: 1.5014x; 1.5014x over previous
#include <cuda_runtime.h>
#include <cuda_fp16.h>
#include <cstdint>

// Problem constants
#define BB 4
#define SS 8192
#define DD 512
#define HH 8
#define HDIM 64
#define RR 64
#define BSROWS (BB * SS)      // 32768
#define BH (BB * HH)          // 32
#define NCHUNK 8

// -------- scratch (static device globals; no allocation) --------
__device__ __half g_xhi[BSROWS * DD];
__device__ __half g_xlo[BSROWS * DD];
__device__ __half g_vh[BSROWS * DD];
__device__ __half g_ahi[BSROWS * DD];
__device__ __half g_wth[4 * DD * DD];     // fp16 transposed weights
__device__ float g_biasqkv[3 * DD];
__device__ __half g_gint_hi[2][128 * 64];
__device__ __half g_gint_lo[2][128 * 64];
__device__ __half g_pqh[BH * SS * RR];    // phiq [bh][s][r], fp16 hi only
__device__ __half g_pkth[BH * RR * SS];   // phikT [bh][r][s], fp16 hi only
__device__ float g_kvtp[BH * NCHUNK * HDIM * RR];
__device__ float g_ksp[BH * NCHUNK * RR];
__device__ __half g_kvth[BH * HDIM * RR];
__device__ float g_ks[BH * RR];

// ============================================================
// helpers
// ============================================================
__device__ __forceinline__ uint32_t smem_to_u32(const void* p) {
    uint32_t a;
    asm("{ .reg .u64 t; cvta.to.shared.u64 t, %1; cvt.u32.u64 %0, t; }"
        : "=r"(a) : "l"(p));
    return a;
}
__device__ __forceinline__ void ldsm4(uint32_t& r0, uint32_t& r1,
                                      uint32_t& r2, uint32_t& r3,
                                      uint32_t addr) {
    asm volatile("ldmatrix.sync.aligned.m8n8.x4.shared.b16 {%0,%1,%2,%3}, [%4];"
                 : "=r"(r0), "=r"(r1), "=r"(r2), "=r"(r3) : "r"(addr));
}
__device__ __forceinline__ void ldsm4t(uint32_t& r0, uint32_t& r1,
                                       uint32_t& r2, uint32_t& r3,
                                       uint32_t addr) {
    asm volatile("ldmatrix.sync.aligned.m8n8.x4.trans.shared.b16 {%0,%1,%2,%3}, [%4];"
                 : "=r"(r0), "=r"(r1), "=r"(r2), "=r"(r3) : "r"(addr));
}
__device__ __forceinline__ void mma16816(float* d, const uint32_t* a,
                                         const uint32_t* b) {
    asm volatile(
        "mma.sync.aligned.m16n8k16.row.col.f32.f16.f16.f32 "
        "{%0,%1,%2,%3}, {%4,%5,%6,%7}, {%8,%9}, {%0,%1,%2,%3};"
        : "+f"(d[0]), "+f"(d[1]), "+f"(d[2]), "+f"(d[3])
        : "r"(a[0]), "r"(a[1]), "r"(a[2]), "r"(a[3]), "r"(b[0]), "r"(b[1]));
}
#define CP_ASYNC16(dst, src) \
    asm volatile("cp.async.cg.shared.global [%0], [%1], 16;" :: "r"(dst), "l"(src))
#define CP_COMMIT() asm volatile("cp.async.commit_group;" ::: "memory")
#define CP_WAIT(n)  asm volatile("cp.async.wait_group %0;" :: "n"(n) : "memory")

__device__ __forceinline__ void split4h(float4 v, uint2& hi, uint2& lo) {
    __half h0 = __float2half_rn(v.x), h1 = __float2half_rn(v.y);
    __half h2 = __float2half_rn(v.z), h3 = __float2half_rn(v.w);
    float r0 = v.x - __half2float(h0), r1 = v.y - __half2float(h1);
    float r2 = v.z - __half2float(h2), r3 = v.w - __half2float(h3);
    __half l0 = __float2half_rn(r0), l1 = __float2half_rn(r1);
    __half l2 = __float2half_rn(r2), l3 = __float2half_rn(r3);
    hi.x = ((uint32_t)__half_as_ushort(h1) << 16) | __half_as_ushort(h0);
    hi.y = ((uint32_t)__half_as_ushort(h3) << 16) | __half_as_ushort(h2);
    lo.x = ((uint32_t)__half_as_ushort(l1) << 16) | __half_as_ushort(l0);
    lo.y = ((uint32_t)__half_as_ushort(l3) << 16) | __half_as_ushort(l2);
}
__device__ __forceinline__ void split2h(float a, float b, uint32_t& hp, uint32_t& lp) {
    __half h0 = __float2half_rn(a), h1 = __float2half_rn(b);
    float l0 = a - __half2float(h0), l1 = b - __half2float(h1);
    __half e0 = __float2half_rn(l0), e1 = __float2half_rn(l1);
    hp = ((uint32_t)__half_as_ushort(h1) << 16) | __half_as_ushort(h0);
    lp = ((uint32_t)__half_as_ushort(e1) << 16) | __half_as_ushort(e0);
}
__device__ __forceinline__ uint32_t pack2h(float a, float b) {
    __half h0 = __float2half_rn(a), h1 = __float2half_rn(b);
    return ((uint32_t)__half_as_ushort(h1) << 16) | __half_as_ushort(h0);
}

// ============================================================
// prep kernels
// ============================================================
__global__ __launch_bounds__(256) void split_fp32(
    const float* __restrict__ X, __half* __restrict__ Xh,
    __half* __restrict__ Xl)
{
    int i = blockIdx.x * 256 + threadIdx.x;
    float4 v = ((const float4*)X)[i];
    uint2 hi, lo;
    split4h(v, hi, lo);
    ((uint2*)Xh)[i] = hi;
    ((uint2*)Xl)[i] = lo;
}

__global__ __launch_bounds__(256) void transpose_h4(
    const float* __restrict__ Wq, const float* __restrict__ Wk,
    const float* __restrict__ Wv, const float* __restrict__ Wp,
    const float* __restrict__ gq, const float* __restrict__ gk,
    __half* __restrict__ Th)
{
    __shared__ float t[32][33];
    const int z = blockIdx.z;
    const float* W = z == 0 ? Wq : (z == 1 ? Wk : (z == 2 ? Wv : Wp));
    const float scale = z == 0 ? gq[0] : (z == 1 ? gk[0] : 1.0f);
    const int rowoff = z * DD;
    int bx = blockIdx.x * 32, by = blockIdx.y * 32;
    int x = threadIdx.x & 31, y = threadIdx.x >> 5;
    for (int i = y; i < 32; i += 8) t[i][x] = W[(size_t)(by + i) * DD + bx + x];
    __syncthreads();
    for (int i = y; i < 32; i += 8)
        Th[(size_t)(rowoff + bx + i) * DD + by + x] = __float2half_rn(t[x][i] * scale);
}

__global__ __launch_bounds__(256) void misc_prep(
    const float* __restrict__ qG1, const float* __restrict__ qG2,
    const float* __restrict__ kG1, const float* __restrict__ kG2,
    const float* bq, const float* bk, const float* bv,
    const float* gq, const float* betq,
    const float* gk, const float* betk,
    float* bout)
{
    const int blk = blockIdx.x;
    if (blk < 2) {
        const int set = blk;
        const float* G1 = set ? kG1 : qG1;
        const float* G2 = set ? kG2 : qG2;
        __half* Oh = g_gint_hi[set];
        __half* Ol = g_gint_lo[set];
        for (int it = 0; it < 32; it++) {
            int idx = it * 256 + threadIdx.x;
            int n = idx >> 6, k = idx & 63;
            float v = ((n & 1) ? G2 : G1)[k * 64 + (n >> 1)];
            __half h = __float2half_rn(v);
            Oh[idx] = h;
            Ol[idx] = __float2half_rn(v - __half2float(h));
        }
    } else {
        int i = (blk - 2) * 256 + threadIdx.x;
        if (i < DD) bout[i] = gq[0] * bq[i] + betq[0];
        else if (i < 2 * DD) bout[i] = gk[0] * bk[i - DD] + betk[0];
        else if (i < 3 * DD) bout[i] = bv[i - 2 * DD];
    }
}

// ============================================================
// fp16 split GEMM + fused sketch epilogue (R14 structure).
// 512 threads, 16 warps (4m x 4n), warp tile 32x64, CTA 128x256.
// A-lo pass used only when Alo!=null AND bn<2 (q only); k,v are 1-pass.
// ============================================================
#define BKC 32
#define NKCH (DD / BKC)          // 16
#define ROWB 80
#define TILE_A (128 * ROWB)      // 10240
#define TILE_B (256 * ROWB)      // 20480
#define ST_AHI 0
#define ST_ALO TILE_A
#define ST_BH (2 * TILE_A)
#define STAGEB (2 * TILE_A + TILE_B)   // 40960
#define PIPE 4
#define OFF80(row, ch) ((uint32_t)((row) * ROWB + ((ch) << 4)))
#define FZ_HEAD 36864
#define FZ_LO 18432
#define FG_OFF (4 * FZ_HEAD)
#define FG_LO 18432
#define GEMM_SMEM (FG_OFF + 2 * FG_LO)   // 184320
#define SOFF144(row, ch) ((uint32_t)((row) * 144 + ((ch) << 4)))

__global__ __launch_bounds__(512, 1) void mma_gemm(
    const __half* __restrict__ Ahi, const __half* __restrict__ Alo,
    const __half* __restrict__ Bh, const float* __restrict__ bias,
    __half* __restrict__ pqh, __half* __restrict__ pkth,
    __half* __restrict__ vh, float* __restrict__ ofp32)
{
    extern __shared__ char smem[];
    const uint32_t sb = smem_to_u32(smem);

    const int tid = threadIdx.x;
    const int wid = tid >> 5, lane = tid & 31;
    const int bn = blockIdx.x, bm = blockIdx.y;
    const int warp_m = wid & 3, warp_n = wid >> 2;
    const bool useAlo = (Alo != nullptr) && (bn < 2);   // q tiles only

    const __half* Ahi_b = Ahi + (size_t)bm * 128 * DD;
    const __half* Alo_b = useAlo ? Alo + (size_t)bm * 128 * DD : Ahi_b;
    const __half* Bh_b = Bh + (size_t)bn * 256 * DD;

    const int lrow = tid >> 2;    // 0..127
    const int lch = tid & 3;

    auto load_chunk = [&](int c, int s) {
        const uint32_t stg = sb + s * STAGEB;
        const int k0 = c * BKC;
        {
            const size_t go = (size_t)lrow * DD + k0 + lch * 8;
            const uint32_t so = OFF80(lrow, lch);
            CP_ASYNC16(stg + ST_AHI + so, Ahi_b + go);
            if (useAlo) CP_ASYNC16(stg + ST_ALO + so, Alo_b + go);
        }
#pragma unroll
        for (int sw = 0; sw < 2; sw++) {
            const int row = sw * 128 + lrow;
            const size_t go = (size_t)row * DD + k0 + lch * 8;
            CP_ASYNC16(stg + ST_BH + OFF80(row, lch), Bh_b + go);
        }
    };

    float acc[2][8][4];
#pragma unroll
    for (int i = 0; i < 2; i++)
#pragma unroll
        for (int j = 0; j < 8; j++)
#pragma unroll
            for (int e = 0; e < 4; e++) acc[i][j][e] = 0.f;

    const int mat = lane >> 3, mr = lane & 7;
    const int a_row_b = warp_m * 32 + (mat & 1) * 8 + mr;
    const int b_row_b = warp_n * 64 + (mat & 1) * 8 + mr;
    const int mchunk = mat >> 1;

    load_chunk(0, 0); CP_COMMIT();
    load_chunk(1, 1); CP_COMMIT();
    load_chunk(2, 2); CP_COMMIT();

    for (int c = 0; c < NKCH; c++) {
        CP_WAIT(2);
        __syncthreads();
        if (c + 3 < NKCH) load_chunk(c + 3, (c + 3) % PIPE);
        CP_COMMIT();

        const uint32_t stg = sb + (c % PIPE) * STAGEB;
#pragma unroll
        for (int kk = 0; kk < 2; kk++) {
            const int ch = kk * 2 + mchunk;
            uint32_t ahi[2][4], alo[2][4];
#pragma unroll
            for (int im = 0; im < 2; im++) {
                const int row = a_row_b + im * 16;
                ldsm4(ahi[im][0], ahi[im][1], ahi[im][2], ahi[im][3],
                      stg + ST_AHI + OFF80(row, ch));
                if (useAlo)
                    ldsm4(alo[im][0], alo[im][1], alo[im][2], alo[im][3],
                          stg + ST_ALO + OFF80(row, ch));
            }
#pragma unroll
            for (int j16 = 0; j16 < 4; j16++) {
                const int row = b_row_b + j16 * 16;
                uint32_t h0, h1, h2, h3;
                ldsm4(h0, h1, h2, h3, stg + ST_BH + OFF80(row, ch));
                uint32_t bh0[2] = {h0, h2}, bh1[2] = {h1, h3};
#pragma unroll
                for (int im = 0; im < 2; im++) {
                    mma16816(acc[im][j16 * 2], ahi[im], bh0);
                    mma16816(acc[im][j16 * 2 + 1], ahi[im], bh1);
                    if (useAlo) {
                        mma16816(acc[im][j16 * 2], alo[im], bh0);
                        mma16816(acc[im][j16 * 2 + 1], alo[im], bh1);
                    }
                }
            }
        }
    }

    const int erow = lane >> 2, ecol = (lane & 3) * 2;

    if (ofp32) {
        const int colbase = bn * 256;
#pragma unroll
        for (int im = 0; im < 2; im++) {
            const size_t row0 = (size_t)bm * 128 + warp_m * 32 + im * 16 + erow;
#pragma unroll
            for (int t = 0; t < 8; t++) {
                const int cofs = warp_n * 64 + t * 8 + ecol;
                float2 b2 = *(const float2*)&bias[colbase + cofs];
                float2 q0 = make_float2(acc[im][t][0] + b2.x, acc[im][t][1] + b2.y);
                float2 q1 = make_float2(acc[im][t][2] + b2.x, acc[im][t][3] + b2.y);
                *(float2*)&ofp32[row0 * DD + colbase + cofs] = q0;
                *(float2*)&ofp32[(row0 + 8) * DD + colbase + cofs] = q1;
            }
        }
        return;
    }

    const int sel = bn >> 1;
    if (sel == 2) {
        const int colbase = (bn & 1) * 256;
#pragma unroll
        for (int im = 0; im < 2; im++) {
            const size_t row0 = (size_t)bm * 128 + warp_m * 32 + im * 16 + erow;
#pragma unroll
            for (int t = 0; t < 8; t++) {
                const int cofs = warp_n * 64 + t * 8 + ecol;
                float2 b2 = *(const float2*)&bias[bn * 256 + cofs];
                *(uint32_t*)(vh + row0 * DD + colbase + cofs) =
                    pack2h(acc[im][t][0] + b2.x, acc[im][t][1] + b2.y);
                *(uint32_t*)(vh + (row0 + 8) * DD + colbase + cofs) =
                    pack2h(acc[im][t][2] + b2.x, acc[im][t][3] + b2.y);
            }
        }
        return;
    }

    // ---- fused sketch epilogue (sel 0 = q, 1 = k) ----
    CP_WAIT(0);
    __syncthreads();

#pragma unroll
    for (int im = 0; im < 2; im++) {
        const int row = warp_m * 32 + im * 16 + erow;
#pragma unroll
        for (int t = 0; t < 8; t++) {
            const int cofs = warp_n * 64 + t * 8 + ecol;
            const int head = cofs >> 6, c = cofs & 63;
            float2 b2 = *(const float2*)&bias[bn * 256 + cofs];
            uint32_t hp, lp;
            split2h(acc[im][t][0] + b2.x, acc[im][t][1] + b2.y, hp, lp);
            *(uint32_t*)(smem + head * FZ_HEAD + row * 144 + c * 2) = hp;
            *(uint32_t*)(smem + head * FZ_HEAD + FZ_LO + row * 144 + c * 2) = lp;
            split2h(acc[im][t][2] + b2.x, acc[im][t][3] + b2.y, hp, lp);
            *(uint32_t*)(smem + head * FZ_HEAD + (row + 8) * 144 + c * 2) = hp;
            *(uint32_t*)(smem + head * FZ_HEAD + FZ_LO + (row + 8) * 144 + c * 2) = lp;
        }
    }
    {
        const __half* Gh = &g_gint_hi[sel][0];
        const __half* Gl = &g_gint_lo[sel][0];
#pragma unroll
        for (int it = 0; it < 2; it++) {
            const int cidx = it * 512 + tid;
            const int row = cidx >> 3, ch = cidx & 7;
            *(uint4*)(smem + FG_OFF + SOFF144(row, ch)) =
                *(const uint4*)((const char*)Gh + row * 128 + ch * 16);
            *(uint4*)(smem + FG_OFF + FG_LO + SOFF144(row, ch)) =
                *(const uint4*)((const char*)Gl + row * 128 + ch * 16);
        }
    }
    __syncthreads();

    const int swm = wid & 3, swn = wid >> 2;
    const int a_row_s = swm * 32 + (mat & 1) * 8 + mr;
    const int b_row_s = swn * 32 + (mat & 1) * 8 + mr;
    const int b = bm >> 6;
    const int sbase = (bm & 63) * 128;
    const int g = lane >> 2, t4 = lane & 3;
    const float inv = 0.125f;

    for (int hd = 0; hd < 4; hd++) {
        const uint32_t zb = sb + hd * FZ_HEAD;

        float sk[2][4][4];
#pragma unroll
        for (int i = 0; i < 2; i++)
#pragma unroll
            for (int j = 0; j < 4; j++)
#pragma unroll
                for (int e = 0; e < 4; e++) sk[i][j][e] = 0.f;

#pragma unroll
        for (int kk = 0; kk < 4; kk++) {
            const int ch = kk * 2 + mchunk;
            uint32_t zhi[2][4], zlo[2][4];
#pragma unroll
            for (int im = 0; im < 2; im++) {
                const int row = a_row_s + im * 16;
                ldsm4(zhi[im][0], zhi[im][1], zhi[im][2], zhi[im][3],
                      zb + SOFF144(row, ch));
                ldsm4(zlo[im][0], zlo[im][1], zlo[im][2], zlo[im][3],
                      zb + FZ_LO + SOFF144(row, ch));
            }
#pragma unroll
            for (int j16 = 0; j16 < 2; j16++) {
                const int row = b_row_s + j16 * 16;
                uint32_t h0, h1, h2, h3, l0, l1, l2, l3;
                ldsm4(h0, h1, h2, h3, sb + FG_OFF + SOFF144(row, ch));
                ldsm4(l0, l1, l2, l3, sb + FG_OFF + FG_LO + SOFF144(row, ch));
                uint32_t gh0[2] = {h0, h2}, gh1[2] = {h1, h3};
                uint32_t gl0[2] = {l0, l2}, gl1[2] = {l1, l3};
#pragma unroll
                for (int im = 0; im < 2; im++) {
                    mma16816(sk[im][j16 * 2], zhi[im], gh0);
                    mma16816(sk[im][j16 * 2], zhi[im], gl0);
                    mma16816(sk[im][j16 * 2], zlo[im], gh0);
                    mma16816(sk[im][j16 * 2 + 1], zhi[im], gh1);
                    mma16816(sk[im][j16 * 2 + 1], zhi[im], gl1);
                    mma16816(sk[im][j16 * 2 + 1], zlo[im], gh1);
                }
            }
        }

        const int h = (bn & 1) * 4 + hd;
        const int bh2 = b * HH + h;
        __syncthreads();

        __half* SH = (__half*)(smem + hd * FZ_HEAD);
        if (sel == 0) {
#pragma unroll
            for (int im = 0; im < 2; im++) {
                const int s0 = swm * 32 + im * 16 + g;
#pragma unroll
                for (int jn = 0; jn < 4; jn++) {
                    const int r = swn * 16 + jn * 4 + t4;
                    float h0 = inv * sk[im][jn][0] * sk[im][jn][1];
                    float h1 = inv * sk[im][jn][2] * sk[im][jn][3];
                    SH[s0 * 72 + r] = __float2half_rn(h0 * h0);
                    SH[(s0 + 8) * 72 + r] = __float2half_rn(h1 * h1);
                }
            }
            __syncthreads();
            const int row = tid >> 2, q4 = tid & 3;
            size_t gbase = ((size_t)bh2 * SS + sbase + row) * RR + q4 * 16;
            const uint4* srcH = (const uint4*)(smem + hd * FZ_HEAD + row * 144 + q4 * 32);
            ((uint4*)(pqh + gbase))[0] = srcH[0];
            ((uint4*)(pqh + gbase))[1] = srcH[1];
        } else {
#pragma unroll
            for (int im = 0; im < 2; im++) {
                const int s0 = swm * 32 + im * 16 + g;
#pragma unroll
                for (int jn = 0; jn < 4; jn++) {
                    const int r = swn * 16 + jn * 4 + t4;
                    float h0 = inv * sk[im][jn][0] * sk[im][jn][1];
                    float h1 = inv * sk[im][jn][2] * sk[im][jn][3];
                    SH[r * 136 + s0] = __float2half_rn(h0 * h0);
                    SH[r * 136 + s0 + 8] = __float2half_rn(h1 * h1);
                }
            }
            __syncthreads();
            const int r = tid >> 3, q8 = tid & 7;
            size_t gbase = ((size_t)bh2 * RR + r) * SS + sbase + q8 * 16;
            const uint4* srcH = (const uint4*)(smem + hd * FZ_HEAD + r * 272 + q8 * 32);
            ((uint4*)(pkth + gbase))[0] = srcH[0];
            ((uint4*)(pkth + gbase))[1] = srcH[1];
        }
    }
}

// ============================================================
// TC kvsum (1-pass, cp.async double-buffered steps; NCHUNK=8 -> 16 steps)
// ============================================================
#define KV_STG 18432
#define KV_VHI 0
#define KV_PKH 9216
#define KV_STEPS (SS / NCHUNK / 64)   // 16

__global__ __launch_bounds__(256) void kvsum_tc(
    const __half* __restrict__ pkth, const __half* __restrict__ vh,
    float* __restrict__ kvtp, float* __restrict__ ksp)
{
    __shared__ __align__(16) char sm[2 * KV_STG];   // 36864
    const uint32_t sb = smem_to_u32(sm);

    const int tid = threadIdx.x;
    const int wid = tid >> 5, lane = tid & 31;
    const int chunk = blockIdx.x, bh = blockIdx.y;
    const int b = bh >> 3, h = bh & 7;
    const int warp_m = wid & 1, warp_n = wid >> 1;
    const int mat = lane >> 3, mr = lane & 7;
    const int g = lane >> 2, t = lane & 3;

    float acc[2][2][4];
#pragma unroll
    for (int i = 0; i < 2; i++)
#pragma unroll
        for (int j = 0; j < 2; j++)
#pragma unroll
            for (int e = 0; e < 4; e++) acc[i][j][e] = 0.f;
    float kacc = 0.f;

    const int lr = tid >> 2, lq = tid & 3;
    const int kr = tid & 63, kg = tid >> 6;

    auto load_step = [&](int step, int s) {
        const uint32_t stg = sb + s * KV_STG;
        const int s0 = chunk * (SS / NCHUNK) + step * 64;
        const size_t vo = (size_t)(b * SS + s0 + lr) * DD + h * HDIM + lq * 16;
        CP_ASYNC16(stg + KV_VHI + lr * 144 + lq * 32, vh + vo);
        CP_ASYNC16(stg + KV_VHI + lr * 144 + lq * 32 + 16, vh + vo + 8);
        const size_t po = ((size_t)bh * RR + lr) * SS + s0 + lq * 16;
        CP_ASYNC16(stg + KV_PKH + lr * 144 + lq * 32, pkth + po);
        CP_ASYNC16(stg + KV_PKH + lr * 144 + lq * 32 + 16, pkth + po + 8);
    };

    load_step(0, 0);
    CP_COMMIT();

    for (int step = 0; step < KV_STEPS; step++) {
        if (step + 1 < KV_STEPS) load_step(step + 1, (step + 1) & 1);
        CP_COMMIT();
        CP_WAIT(1);
        __syncthreads();

        const uint32_t stg = sb + (step & 1) * KV_STG;

#pragma unroll
        for (int c = 0; c < 16; c++) {
            int sc = kg * 16 + c;
            kacc += __half2float(*(__half*)((char*)sm + (step & 1) * KV_STG +
                                            KV_PKH + kr * 144 + sc * 2));
        }

#pragma unroll
        for (int kk = 0; kk < 4; kk++) {
            uint32_t ah[2][4];
#pragma unroll
            for (int im = 0; im < 2; im++) {
                const int d0 = warp_m * 32 + im * 16 + (mat & 1) * 8;
                const int srow = kk * 16 + ((mat >> 1) & 1) * 8 + mr;
                ldsm4t(ah[im][0], ah[im][1], ah[im][2], ah[im][3],
                       stg + KV_VHI + srow * 144 + d0 * 2);
            }
            const int rrow = warp_n * 16 + (mat & 1) * 8 + mr;
            const int chb = kk * 2 + (mat >> 1);
            uint32_t h0, h1, h2, h3;
            ldsm4(h0, h1, h2, h3, stg + KV_PKH + rrow * 144 + chb * 16);
            uint32_t bh0[2] = {h0, h2}, bh1[2] = {h1, h3};
#pragma unroll
            for (int im = 0; im < 2; im++) {
                mma16816(acc[im][0], ah[im], bh0);
                mma16816(acc[im][1], ah[im], bh1);
            }
        }
        __syncthreads();
    }

    float* outp = kvtp + ((size_t)bh * NCHUNK + chunk) * (HDIM * RR);
#pragma unroll
    for (int im = 0; im < 2; im++) {
        const int d = warp_m * 32 + im * 16 + g;
#pragma unroll
        for (int nb = 0; nb < 2; nb++) {
            const int r = warp_n * 16 + nb * 8 + t * 2;
            *(float2*)&outp[d * RR + r] =
                make_float2(acc[im][nb][0], acc[im][nb][1]);
            *(float2*)&outp[(d + 8) * RR + r] =
                make_float2(acc[im][nb][2], acc[im][nb][3]);
        }
    }
    __syncthreads();
    float* red = (float*)sm;
    red[kg * 64 + kr] = kacc;
    __syncthreads();
    if (tid < 64)
        ksp[((size_t)bh * NCHUNK + chunk) * RR + tid] =
            red[tid] + red[64 + tid] + red[128 + tid] + red[192 + tid];
}

__global__ void reduce2(const float* __restrict__ kvtp,
                        const float* __restrict__ ksp,
                        __half* __restrict__ kvth, float* __restrict__ ks)
{
    const int idx = blockIdx.x * 256 + threadIdx.x;
    const int total = BH * HDIM * RR;
    if (idx < total) {
        int bh = idx >> 12, e = idx & 4095;
        float s = 0.f;
#pragma unroll
        for (int c = 0; c < NCHUNK; c++)
            s += kvtp[((size_t)bh * NCHUNK + c) * 4096 + e];
        kvth[idx] = __float2half_rn(s);
    } else if (idx < total + BH * RR) {
        int j = idx - total;
        int bh = j >> 6, r = j & 63;
        float s = 0.f;
#pragma unroll
        for (int c = 0; c < NCHUNK; c++)
            s += ksp[((size_t)bh * NCHUNK + c) * RR + r];
        ks[j] = s;
    }
}

// ============================================================
// TC attn: 256 s-rows per CTA, one kv load, two MMA halves.
// ============================================================
#define AT_PQH 0
#define AT_KVH (256 * 144)                 // 36864
#define AT_KS  (AT_KVH + 64 * 144)         // + 9216
#define AT_DEN (AT_KS + 256)
#define AT_SMEM (AT_DEN + 1024)            // 47360

__global__ __launch_bounds__(256) void attn_tc(
    const __half* __restrict__ pqh, const __half* __restrict__ kvth,
    const float* __restrict__ ks,
    __half* __restrict__ ahi)
{
    __shared__ __align__(16) char sm[AT_SMEM];
    const uint32_t sb = smem_to_u32(sm);
    const int tid = threadIdx.x;
    const int wid = tid >> 5, lane = tid & 31;
    const int stile = blockIdx.x, bh = blockIdx.y;
    const int b = bh >> 3, h = bh & 7;
    const int sbase = stile * 256;
    const int warp_m = wid >> 1, warp_n = wid & 1;

    {
        const int row = tid;
        size_t gbase = ((size_t)bh * SS + sbase + row) * RR;
        uint4* dst = (uint4*)(sm + AT_PQH + row * 144);
#pragma unroll
        for (int i = 0; i < 8; i++) dst[i] = ((const uint4*)(pqh + gbase))[i];
    }
    {
        const int row = tid >> 2, q4 = tid & 3;
        size_t gbase = (size_t)bh * (HDIM * RR) + row * RR + q4 * 16;
        *(uint4*)(sm + AT_KVH + row * 144 + q4 * 32) = *(const uint4*)(kvth + gbase);
        *(uint4*)(sm + AT_KVH + row * 144 + q4 * 32 + 16) = *(const uint4*)(kvth + gbase + 8);
    }
    if (tid < 64) ((float*)(sm + AT_KS))[tid] = ks[bh * RR + tid];
    __syncthreads();

    {
        float d = 1e-6f;
        const float* kss = (const float*)(sm + AT_KS);
#pragma unroll 16
        for (int r = 0; r < 64; r++) {
            float p = __half2float(*(__half*)(sm + AT_PQH + tid * 144 + r * 2));
            d += p * kss[r];
        }
        ((float*)(sm + AT_DEN))[tid] = 1.0f / d;
    }
    __syncthreads();

    const int mat = lane >> 3, mr = lane & 7;
    const int b_row_b = warp_n * 32 + (mat & 1) * 8 + mr;
    const int mchunk = mat >> 1;
    const int g = lane >> 2, t = lane & 3;
    const float* rden = (const float*)(sm + AT_DEN);

#pragma unroll
    for (int half = 0; half < 2; half++) {
        const int hbase = half * 128;
        const int a_row_b = hbase + warp_m * 32 + (mat & 1) * 8 + mr;

        float acc[2][4][4];
#pragma unroll
        for (int i = 0; i < 2; i++)
#pragma unroll
            for (int j = 0; j < 4; j++)
#pragma unroll
                for (int e = 0; e < 4; e++) acc[i][j][e] = 0.f;

#pragma unroll
        for (int kk = 0; kk < 4; kk++) {
            const int ch = kk * 2 + mchunk;
            uint32_t ah[2][4];
#pragma unroll
            for (int im = 0; im < 2; im++) {
                const int row = a_row_b + im * 16;
                ldsm4(ah[im][0], ah[im][1], ah[im][2], ah[im][3],
                      sb + AT_PQH + row * 144 + ch * 16);
            }
#pragma unroll
            for (int nt = 0; nt < 2; nt++) {
                const int row = b_row_b + nt * 16;
                uint32_t h0, h1, h2, h3;
                ldsm4(h0, h1, h2, h3, sb + AT_KVH + row * 144 + ch * 16);
                uint32_t bh0[2] = {h0, h2}, bh1[2] = {h1, h3};
#pragma unroll
                for (int im = 0; im < 2; im++) {
                    mma16816(acc[im][nt * 2], ah[im], bh0);
                    mma16816(acc[im][nt * 2 + 1], ah[im], bh1);
                }
            }
        }

#pragma unroll
        for (int im = 0; im < 2; im++) {
            const int s0 = hbase + warp_m * 32 + im * 16 + g;
            const float rd0 = rden[s0], rd1 = rden[s0 + 8];
            const size_t row0 = ((size_t)b * SS + sbase + s0) * DD + h * HDIM;
            const size_t row1 = row0 + 8 * DD;
#pragma unroll
            for (int j8 = 0; j8 < 4; j8++) {
                const int d = warp_n * 32 + j8 * 8 + t * 2;
                *(uint32_t*)(ahi + row0 + d) =
                    pack2h(acc[im][j8][0] * rd0, acc[im][j8][1] * rd0);
                *(uint32_t*)(ahi + row1 + d) =
                    pack2h(acc[im][j8][2] * rd1, acc[im][j8][3] * rd1);
            }
        }
    }
}

// ============================================================
// launch
// ============================================================
extern "C" void kernel_launch(void* const* d_in, const int* in_sizes, int n_in,
                              void* d_out, int out_size)
{
    const float* x       = (const float*)d_in[0];
    const float* Wq      = (const float*)d_in[1];
    const float* bq      = (const float*)d_in[2];
    const float* Wk      = (const float*)d_in[3];
    const float* bk      = (const float*)d_in[4];
    const float* Wv      = (const float*)d_in[5];
    const float* bv      = (const float*)d_in[6];
    const float* Wp      = (const float*)d_in[7];
    const float* bp      = (const float*)d_in[8];
    const float* gamma_q = (const float*)d_in[9];
    const float* beta_q  = (const float*)d_in[10];
    const float* gamma_k = (const float*)d_in[11];
    const float* beta_k  = (const float*)d_in[12];
    const float* qG1     = (const float*)d_in[13];
    const float* qG2     = (const float*)d_in[14];
    const float* kG1     = (const float*)d_in[15];
    const float* kG2     = (const float*)d_in[16];
    float* out = (float*)d_out;

    float *p_bqkv, *p_kvtp, *p_ksp, *p_ks;
    __half *p_xhi, *p_xlo, *p_vh, *p_ahi, *p_wth;
    __half *p_pqh, *p_pkth, *p_kvth;
    cudaGetSymbolAddress((void**)&p_xhi, g_xhi);
    cudaGetSymbolAddress((void**)&p_xlo, g_xlo);
    cudaGetSymbolAddress((void**)&p_vh, g_vh);
    cudaGetSymbolAddress((void**)&p_ahi, g_ahi);
    cudaGetSymbolAddress((void**)&p_wth, g_wth);
    cudaGetSymbolAddress((void**)&p_bqkv, g_biasqkv);
    cudaGetSymbolAddress((void**)&p_pqh, g_pqh);
    cudaGetSymbolAddress((void**)&p_pkth, g_pkth);
    cudaGetSymbolAddress((void**)&p_kvtp, g_kvtp);
    cudaGetSymbolAddress((void**)&p_ksp, g_ksp);
    cudaGetSymbolAddress((void**)&p_kvth, g_kvth);
    cudaGetSymbolAddress((void**)&p_ks, g_ks);

    cudaFuncSetAttribute(mma_gemm, cudaFuncAttributeMaxDynamicSharedMemorySize,
                         GEMM_SMEM);

    // ---- prep (3 launches) ----
    split_fp32<<<BSROWS * DD / 4 / 256, 256>>>(x, p_xhi, p_xlo);               // 1
    misc_prep<<<8, 256>>>(qG1, qG2, kG1, kG2, bq, bk, bv,
                          gamma_q, beta_q, gamma_k, beta_k, p_bqkv);           // 2
    transpose_h4<<<dim3(16, 16, 4), 256>>>(Wq, Wk, Wv, Wp,
                                           gamma_q, gamma_k, p_wth);           // 3

    // ---- fused QKV GEMM + sketch (512 thr; q 2-pass, k/v 1-pass) ----
    dim3 gq(6, BSROWS / 128);
    mma_gemm<<<gq, 512, GEMM_SMEM>>>(p_xhi, p_xlo, p_wth, p_bqkv,
                                     p_pqh, p_pkth, p_vh, nullptr);            // 4

    // ---- TC kvsum (pipelined, NCHUNK=8) + reduce ----
    kvsum_tc<<<dim3(NCHUNK, BH), 256>>>(p_pkth, p_vh, p_kvtp, p_ksp);          // 5
    int red_total = BH * HDIM * RR + BH * RR;
    reduce2<<<(red_total + 255) / 256, 256>>>(p_kvtp, p_ksp, p_kvth, p_ks);

    // ---- TC attention output (256 rows/CTA, fp16 out) ----
    attn_tc<<<dim3(SS / 256, BH), 256>>>(p_pqh, p_kvth, p_ks, p_ahi);

    // ---- output projection (1-pass fp16, fp32 out) ----
    dim3 go(2, BSROWS / 128);
    mma_gemm<<<go, 512, GEMM_SMEM>>>(p_ahi, nullptr, p_wth + 1536 * DD, bp,
                                     nullptr, nullptr, nullptr, out);
}